// round 17
// baseline (speedup 1.0000x reference)
#include <cuda_runtime.h>
#include <math_constants.h>
#include <cstdint>

typedef unsigned long long ULL;

#define Bc 1024
#define Sc 2048
#define Hc 50
#define TT 32
#define NTILE 64
#define NTH 64
#define RS 60
#define L2E 1.4426950408889634f

// ---- dynamic SMEM layout (bytes), 16576/CTA -> 8 CTAs/SM ----
#define OFF_BUF0  0                // float[32*60]  7680
#define OFF_BUF1  7680             // float[32*60]  7680
// (bfrag transient: 14336 B spanning BUF0..BUF1 during setup)
#define OFF_WS    15360            // float[64]      256
#define OFF_SPART 15616            // float[2*32]    256
#define OFF_PPV   OFF_SPART        // overlay: setup only
#define OFF_MBITS 15872            // u32[64]        256
#define OFF_SL    16128            // float[2]        32
#define OFF_SCTX  16160            // ULL[2][25]     400
#define SMEM_BYTES 16576

__device__ __forceinline__ uint32_t smem_u32(const void* p) {
    uint32_t a;
    asm("{ .reg .u64 t; cvta.to.shared.u64 t, %1; cvt.u32.u64 %0, t; }" : "=r"(a) : "l"(p));
    return a;
}
__device__ __forceinline__ float fast_ex2(float x) {
    float r; asm("ex2.approx.f32 %0, %1;" : "=f"(r) : "f"(x)); return r;
}
__device__ __forceinline__ float fast_tanh(float x) {
    float r; asm("tanh.approx.f32 %0, %1;" : "=f"(r) : "f"(x)); return r;
}
__device__ __forceinline__ ULL pack2(float lo, float hi) {
    ULL r; asm("mov.b64 %0, {%1, %2};" : "=l"(r) : "f"(lo), "f"(hi)); return r;
}
__device__ __forceinline__ void unpack2(ULL v, float& lo, float& hi) {
    asm("mov.b64 {%0, %1}, %2;" : "=f"(lo), "=f"(hi) : "l"(v));
}
#define FMA2(d, a, b) asm("fma.rn.f32x2 %0, %1, %2, %0;" : "+l"(d) : "l"(a), "l"(b))
__device__ __forceinline__ ULL add2(ULL a, ULL b) {
    ULL r; asm("add.rn.f32x2 %0, %1, %2;" : "=l"(r) : "l"(a), "l"(b)); return r;
}
__device__ __forceinline__ uint32_t to_tf32(float v) {
    uint32_t u; asm("cvt.rna.tf32.f32 %0, %1;" : "=r"(u) : "f"(v)); return u;
}

#define MMA_TF32(C, A, B0, B1)                                                  \
    asm("mma.sync.aligned.m16n8k8.row.col.f32.tf32.tf32.f32 "                   \
        "{%0,%1,%2,%3}, {%4,%5,%6,%7}, {%8,%9}, {%0,%1,%2,%3};"                 \
        : "+f"((C)[0]), "+f"((C)[1]), "+f"((C)[2]), "+f"((C)[3])                \
        : "r"((A)[0]), "r"((A)[1]), "r"((A)[2]), "r"((A)[3]), "r"(B0), "r"(B1))

#define CP_ASYNC8(dst, src) \
    asm volatile("cp.async.ca.shared.global [%0], [%1], 8;" :: "r"(dst), "l"(src))
#define CP_COMMIT() asm volatile("cp.async.commit_group;" ::: "memory")
#define CP_WAIT0()  asm volatile("cp.async.wait_group 0;" ::: "memory")

#define STAGE_ROWS(dst0, src0, CNT) do {                                        \
    _Pragma("unroll")                                                           \
    for (int i = 0; i < (CNT); i++)                                             \
        CP_ASYNC8((dst0) + i * (RS * 4), (src0) + (size_t)i * tok_stride);      \
} while (0)

#define CTX_ROWS(CNT) do {                                                      \
    _Pragma("unroll")                                                           \
    for (int r = 0; r < (CNT); r += 2) {                                        \
        float p0 = __shfl_sync(0xffffffffu, pv, r);                             \
        float p1 = __shfl_sync(0xffffffffu, pv, r + 1);                         \
        lwA += p0;                                                              \
        lwB += p1;                                                              \
        if (lane < 25) {                                                        \
            ULL e0 = *reinterpret_cast<const ULL*>(crow + r * RS);              \
            ULL e1 = *reinterpret_cast<const ULL*>(crow + (r + 1) * RS);        \
            FMA2(ctxA, pack2(p0, p0), e0);                                      \
            FMA2(ctxB, pack2(p1, p1), e1);                                      \
        }                                                                       \
    }                                                                           \
} while (0)

__global__ __launch_bounds__(NTH, 8)
void additive_attn_kernel(const float* __restrict__ dec,
                          const float* __restrict__ enc,     // (S,B,H)
                          const int*   __restrict__ mask,    // (B,S)
                          const float* __restrict__ Wp,
                          const float* __restrict__ We,
                          const float* __restrict__ Ws,
                          float* __restrict__ out)
{
    extern __shared__ __align__(16) char smem[];
    const uint32_t smb = smem_u32(smem);
    float*    ws    = (float*)(smem + OFF_WS);
    float*    ppv   = (float*)(smem + OFF_PPV);
    float*    spart = (float*)(smem + OFF_SPART);
    uint32_t* mbits = (uint32_t*)(smem + OFF_MBITS);
    float*    sl    = (float*)(smem + OFF_SL);
    ULL (*sctx)[25] = (ULL(*)[25])(smem + OFF_SCTX);

    const int b    = blockIdx.x;
    const int tid  = threadIdx.x;
    const int lane = tid & 31;
    const int wid  = tid >> 5;     // 0..1
    const int g    = lane >> 2;
    const int c    = lane & 3;
    const int wc   = wid;          // n half (0 = heavy: 4 n-blocks; 1 = light: 3)

    // ---- load-balance split: heavy warp 12 ctx/staging rows, light 20 ----
    const int rstart = wc ? 12 : 0;
    const int rcnt_c = wc ? 20 : 12;
    const int msh    = wc ? 12 : 0;

    // ---- setup: pp, ws ----
    {
        float pp = 0.0f;
        if (tid < Hc) {
            #pragma unroll
            for (int k = 0; k < Hc; k++)
                pp = fmaf(Wp[tid * Hc + k], dec[b * Hc + k], pp);
        }
        ppv[tid] = pp;
        ws[tid]  = (tid < Hc) ? Ws[tid] : 0.0f;
    }
    // ---- pack mask row into bitmask (2048 bits = 64 u32, natural order) ----
    #pragma unroll
    for (int chunk = 0; chunk < 32; chunk++) {
        int m = mask[(size_t)b * Sc + chunk * 64 + tid];
        unsigned bal = __ballot_sync(0xffffffffu, m != 0);
        if (lane == 0) mbits[chunk * 2 + wid] = bal;
    }
    __syncthreads();

    // ---- build B fragments (fragment-major, tf32) transiently in buf0+buf1 ----
    uint32_t* bfrag = (uint32_t*)(smem + OFF_BUF0);
    for (int i = tid; i < 7 * 8 * 32 * 2; i += NTH) {
        int r  = i & 1;
        int ln = (i >> 1) & 31;
        int nb = (i >> 6) & 7;
        int s  = i >> 9;
        int k  = 8 * s + (ln & 3) + 4 * r;
        int n  = nb * 8 + (ln >> 2);
        float v = 0.0f;
        if (n < Hc) {
            if (k < Hc)       v = We[n * Hc + k];
            else if (k == 50) v = ppv[n];
        }
        bfrag[i] = to_tf32(v);
    }
    __syncthreads();

    // ---- hoist B frags + ws to registers ----
    uint2 Breg[7][4];
    #pragma unroll
    for (int s = 0; s < 7; s++)
        #pragma unroll
        for (int nb = 0; nb < 4; nb++)
            Breg[s][nb] = *reinterpret_cast<const uint2*>(
                bfrag + s * 512 + (wc * 4 + nb) * 64 + lane * 2);
    float wsr[4][2];
    #pragma unroll
    for (int nb = 0; nb < 4; nb++) {
        wsr[nb][0] = ws[wc * 32 + nb * 8 + 2 * c];
        wsr[nb][1] = ws[wc * 32 + nb * 8 + 2 * c + 1];
    }
    __syncthreads();   // done reading bfrag; buffers free

    // ---- init pad cols 50..59 in BOTH buffers ----
    for (int i = tid; i < TT * 10; i += NTH) {
        int t = i / 10, cc = i - 10 * (i / 10);
        float v = (cc == 0) ? 1.0f : 0.0f;          // col 50 = 1.0 (pp lane)
        ((float*)(smem + OFF_BUF0))[t * RS + 50 + cc] = v;
        ((float*)(smem + OFF_BUF1))[t * RS + 50 + cc] = v;
    }

    // ---- staging geometry: lane = 8B chunk (0..24), rows [rstart, rstart+cnt) ----
    const float* encb = enc + (size_t)b * Hc;
    const bool st_on = (lane < 25);
    const size_t tok_stride = (size_t)(Bc * Hc);
    const uint32_t d_off = (uint32_t)(rstart * RS + 2 * lane) * 4u;
    const size_t  s_off = (size_t)rstart * tok_stride + 2 * lane;

    // ---- prologue: prefetch tile 0 into buf0 ----
    if (st_on) {
        const float* s0 = encb + s_off;
        uint32_t d0 = smb + OFF_BUF0 + d_off;
        if (wc == 0) STAGE_ROWS(d0, s0, 12); else STAGE_ROWS(d0, s0, 20);
    }
    CP_COMMIT();

    float lwA = 0.0f, lwB = 0.0f;
    ULL ctxA = 0ull, ctxB = 0ull;
    const bool skip_nb3 = (wc == 1);   // n 56..63 all have ws == 0

    #pragma unroll 1
    for (int tt = 0; tt < NTILE; tt++) {
        const int par = tt & 1;

        CP_WAIT0();        // own prefetch of tile tt landed
        __syncthreads();   // both warps' tile-tt rows visible; prev buf reads done

        // ---- prefetch tile tt+1 into the other buffer (overlaps MMA below) ----
        if (tt + 1 < NTILE && st_on) {
            const float* sn = encb + (size_t)(tt + 1) * TT * tok_stride + s_off;
            uint32_t dn = smb + (par ? OFF_BUF0 : OFF_BUF1) + d_off;
            if (wc == 0) STAGE_ROWS(dn, sn, 12); else STAGE_ROWS(dn, sn, 20);
        }
        CP_COMMIT();

        // mask bits for this tile's 32 tokens (1 LDS broadcast)
        const uint32_t mw = mbits[tt];

        const float* buf = (const float*)(smem + (par ? OFF_BUF1 : OFF_BUF0));
        const float* pA0 = buf + g * RS + c;

        // ---- GEMM: warp = 32 tokens x (32 or 24) n ----
        float C[2][4][4];
        #pragma unroll
        for (int mt = 0; mt < 2; mt++)
            #pragma unroll
            for (int nb = 0; nb < 4; nb++)
                #pragma unroll
                for (int q = 0; q < 4; q++) C[mt][nb][q] = 0.0f;

        #pragma unroll
        for (int s = 0; s < 7; s++) {
            uint32_t A[2][4];
            #pragma unroll
            for (int mt = 0; mt < 2; mt++) {
                const float* p = pA0 + mt * (16 * RS) + 8 * s;
                A[mt][0] = __float_as_uint(p[0]);
                A[mt][1] = __float_as_uint(p[8 * RS]);
                A[mt][2] = __float_as_uint(p[4]);
                A[mt][3] = __float_as_uint(p[8 * RS + 4]);
            }
            #pragma unroll
            for (int nb = 0; nb < 4; nb++) {
                if (nb == 3 && skip_nb3) continue;
                MMA_TF32(C[0][nb], A[0], Breg[s][nb].x, Breg[s][nb].y);
                MMA_TF32(C[1][nb], A[1], Breg[s][nb].x, Breg[s][nb].y);
            }
        }

        // ---- epilogue: part = sum_n ws[n] * tanh(D) ----
        float part[4] = {0.0f, 0.0f, 0.0f, 0.0f};
        #pragma unroll
        for (int mt = 0; mt < 2; mt++)
            #pragma unroll
            for (int nb = 0; nb < 4; nb++) {
                if (nb == 3 && skip_nb3) continue;
                #pragma unroll
                for (int hi = 0; hi < 2; hi++) {
                    part[mt*2+hi] = fmaf(wsr[nb][0], fast_tanh(C[mt][nb][hi*2]),   part[mt*2+hi]);
                    part[mt*2+hi] = fmaf(wsr[nb][1], fast_tanh(C[mt][nb][hi*2+1]), part[mt*2+hi]);
                }
            }
        #pragma unroll
        for (int q = 0; q < 4; q++) {
            part[q] += __shfl_xor_sync(0xffffffffu, part[q], 1);
            part[q] += __shfl_xor_sync(0xffffffffu, part[q], 2);
        }
        if (c == 0) {
            #pragma unroll
            for (int mt = 0; mt < 2; mt++)
                #pragma unroll
                for (int hi = 0; hi < 2; hi++)
                    spart[wc * TT + mt * 16 + hi * 8 + g] = part[mt*2+hi];
        }
        __syncthreads();   // score partials visible

        // ---- exp in-lane (lane<cnt holds token rstart+lane), then context ----
        float pv = 0.0f;
        if (lane < rcnt_c) {
            int t = rstart + lane;
            float sc = spart[t] + spart[TT + t];
            int mk = (mw >> (msh + lane)) & 1;
            pv = mk ? fast_ex2(sc * L2E) : 0.0f;
        }
        const float* crow = buf + rstart * RS + 2 * lane;
        if (wc == 0) CTX_ROWS(12); else CTX_ROWS(20);
    }

    // ---- finalize ----
    ULL   ctx2 = add2(ctxA, ctxB);
    float lw   = lwA + lwB;
    if (lane == 0) sl[wid] = lw;
    if (lane < 25) sctx[wid][lane] = ctx2;
    __syncthreads();
    if (tid < 25) {
        float sx = 0.0f, sy = 0.0f, lt = 0.0f;
        #pragma unroll
        for (int i = 0; i < 2; i++) {
            float x, y; unpack2(sctx[i][tid], x, y);
            sx += x; sy += y; lt += sl[i];
        }
        float inv = 1.0f / lt;
        float2 o; o.x = sx * inv; o.y = sy * inv;
        *reinterpret_cast<float2*>(out + (size_t)b * Hc + 2 * tid) = o;
    }
}

extern "C" void kernel_launch(void* const* d_in, const int* in_sizes, int n_in,
                              void* d_out, int out_size) {
    const float* dec  = (const float*)d_in[0];
    const float* enc  = (const float*)d_in[1];
    const int*   mask = (const int*)  d_in[2];
    const float* Wp   = (const float*)d_in[3];
    const float* We   = (const float*)d_in[4];
    const float* Ws   = (const float*)d_in[5];
    float* out = (float*)d_out;

    cudaFuncSetAttribute(additive_attn_kernel,
                         cudaFuncAttributeMaxDynamicSharedMemorySize, SMEM_BYTES);
    additive_attn_kernel<<<Bc, NTH, SMEM_BYTES>>>(dec, enc, mask, Wp, We, Ws, out);
}